// round 11
// baseline (speedup 1.0000x reference)
#include <cuda_runtime.h>
#include <cuda_bf16.h>
#include <cstdint>

#define D         256
#define KNB       16
#define S_MAX     50000
#define N_MAX     100000

// Static scratch: snapshot of pre-update supports rows [0, S)
__device__ float4        g_snap[(size_t)S_MAX * (D / 4)];
__device__ __nv_bfloat16 g_Whi[D * D];
__device__ __nv_bfloat16 g_Wlo[D * D];

__device__ __forceinline__ uint32_t smem_u32(const void* p) {
    uint32_t a;
    asm("{ .reg .u64 t; cvta.to.shared.u64 t, %1; cvt.u32.u64 %0, t; }" : "=r"(a) : "l"(p));
    return a;
}
__device__ __forceinline__ void ldsm4(uint32_t& r0, uint32_t& r1, uint32_t& r2, uint32_t& r3,
                                      uint32_t addr) {
    asm volatile("ldmatrix.sync.aligned.m8n8.x4.shared.b16 {%0,%1,%2,%3}, [%4];"
                 : "=r"(r0), "=r"(r1), "=r"(r2), "=r"(r3) : "r"(addr));
}
__device__ __forceinline__ void mma16816(float* d, const uint32_t* a, uint32_t b0, uint32_t b1) {
    asm volatile(
        "mma.sync.aligned.m16n8k16.row.col.f32.bf16.bf16.f32 "
        "{%0,%1,%2,%3}, {%4,%5,%6,%7}, {%8,%9}, {%0,%1,%2,%3};"
        : "+f"(d[0]), "+f"(d[1]), "+f"(d[2]), "+f"(d[3])
        : "r"(a[0]), "r"(a[1]), "r"(a[2]), "r"(a[3]), "r"(b0), "r"(b1));
}
__device__ __forceinline__ void cpasync16(uint32_t dst, const void* src) {
    asm volatile("cp.async.cg.shared.global [%0], [%1], 16;" :: "r"(dst), "l"(src));
}
#define CP_COMMIT() asm volatile("cp.async.commit_group;" ::: "memory")
#define CP_WAIT0()  asm volatile("cp.async.wait_group 0;" ::: "memory")

// pack 8 fp32 -> bf16 hi (uint4) and lo (uint4)
__device__ __forceinline__ void split8(const float* f, uint4& hi, uint4& lo) {
    uint32_t h[4], l[4];
#pragma unroll
    for (int i = 0; i < 4; i++) {
        __nv_bfloat16 h0 = __float2bfloat16_rn(f[2 * i + 0]);
        __nv_bfloat16 h1 = __float2bfloat16_rn(f[2 * i + 1]);
        __nv_bfloat16 l0 = __float2bfloat16_rn(f[2 * i + 0] - __bfloat162float(h0));
        __nv_bfloat16 l1 = __float2bfloat16_rn(f[2 * i + 1] - __bfloat162float(h1));
        __nv_bfloat162 hp = __halves2bfloat162(h0, h1);
        __nv_bfloat162 lp = __halves2bfloat162(l0, l1);
        h[i] = *(uint32_t*)&hp;
        l[i] = *(uint32_t*)&lp;
    }
    hi = make_uint4(h[0], h[1], h[2], h[3]);
    lo = make_uint4(l[0], l[1], l[2], l[3]);
}

// ---------------------------------------------------------------------------
// Kernel 0: split W (fp32 -> bf16 hi + lo). Tiny: 64K elements.
// ---------------------------------------------------------------------------
__global__ __launch_bounds__(256) void splitW_kernel(
    const float* __restrict__ src, uint4* __restrict__ hi, uint4* __restrict__ lo, int n8)
{
    int i = blockIdx.x * 256 + threadIdx.x;
    if (i >= n8) return;
    float f[8];
    *(float4*)(f + 0) = *(const float4*)(src + i * 8 + 0);
    *(float4*)(f + 4) = *(const float4*)(src + i * 8 + 4);
    uint4 h, l;
    split8(f, h, l);
    hi[i] = h; lo[i] = l;
}

// ---------------------------------------------------------------------------
// Kernel 1: bf16-split GEMM via mma.sync.
//  - CTA tile 128x256 (full N), 16 warps 2x8, warp tile 64x32
//  - K chunk 32 (8 iterations), double-buffered smem (120 KB)
//  - W tiles via cp.async (overlapped with compute), A fp32 loaded once,
//    converted to bf16 hi/lo in registers
//  - ksub-outer fragment loop to keep live registers < 128
// ---------------------------------------------------------------------------
#define ROWB    80                        // bytes per smem row (32 halfs + 16 pad)
#define A_TILE  (128 * ROWB)              // 10240
#define W_TILE  (256 * ROWB)              // 20480
#define BUF_B   (2 * A_TILE + 2 * W_TILE) // 61440: [Ah, Al, Wh, Wl]
#define SMEM_GEMM_TOTAL (2 * BUF_B)       // 122880

__global__ __launch_bounds__(512) void gemm_mma_kernel(
    const float* __restrict__ A,   // fp32 [M, 256]
    const float* __restrict__ bias,
    float* __restrict__ C, int M, int S)
{
    extern __shared__ char dsm[];
    const int tid  = threadIdx.x;
    const int lane = tid & 31;
    const int wid  = tid >> 5;         // 0..15
    const int wm   = wid & 1;          // 2 slabs of 64 rows
    const int wn   = wid >> 1;         // 8 slabs of 32 cols
    const int row0 = blockIdx.x * 128;

    const uint32_t sb = smem_u32(dsm);

    float acc[4][4][4];
#pragma unroll
    for (int i = 0; i < 4; i++)
#pragma unroll
        for (int j = 0; j < 4; j++)
#pragma unroll
            for (int q = 0; q < 4; q++) acc[i][j][q] = 0.f;

    // A: 128 rows x 32 fp32 per chunk = 4096 floats; 512 thr x 8 floats
    const int lr   = tid >> 2;         // 0..127
    const int sel  = tid & 3;          // 8-float column group
    const int arow = row0 + lr;
    const bool a_ok = arow < M;
    const float* aptr = A + (size_t)arow * D + sel * 8;
    const uint32_t astore = (uint32_t)(lr * ROWB + sel * 16);

    // W via cp.async: 256 rows x 32 halfs per chunk; 512 thr x 16 halfs/matrix
    const int wr   = tid >> 1;         // 0..255
    const int wsel = tid & 1;          // 16-half column group
    const __nv_bfloat16* whp = g_Whi + (size_t)wr * D + wsel * 16;
    const __nv_bfloat16* wlp = g_Wlo + (size_t)wr * D + wsel * 16;
    const uint32_t wstore = (uint32_t)(wr * ROWB + wsel * 32);

    const uint32_t frag_off = (uint32_t)((lane & 15) * ROWB + (lane >> 4) * 16);

    // staging registers for A
    float af[8];

    // prologue: cp.async W chunk 0 -> buf0; load A chunk 0
    {
        uint32_t d0 = sb + 2 * A_TILE + wstore;
        cpasync16(d0,      whp);
        cpasync16(d0 + 16, whp + 8);
        uint32_t d1 = sb + 2 * A_TILE + W_TILE + wstore;
        cpasync16(d1,      wlp);
        cpasync16(d1 + 16, wlp + 8);
        CP_COMMIT();
        if (a_ok) {
            *(float4*)(af + 0) = *(const float4*)(aptr + 0);
            *(float4*)(af + 4) = *(const float4*)(aptr + 4);
        } else {
#pragma unroll
            for (int i = 0; i < 8; i++) af[i] = 0.f;
        }
    }

    for (int c = 0; c < 8; c++) {
        const int cur = c & 1;
        char* base = dsm + cur * BUF_B;

        // convert + store A chunk c
        uint4 ahv, alv;
        split8(af, ahv, alv);
        *(uint4*)(base + 0 * A_TILE + astore) = ahv;
        *(uint4*)(base + 1 * A_TILE + astore) = alv;

        CP_WAIT0();            // W chunk c has landed (this thread's group)
        __syncthreads();       // all threads' A stores + W arrivals visible;
                               // also: all reads of the OTHER buffer are done

        // issue cp.async W chunk c+1 into the other buffer (overlaps compute)
        if (c < 7) {
            const int o = (c + 1) * 32;
            char* nbase = dsm + (cur ^ 1) * BUF_B;
            uint32_t nb = sb + (uint32_t)((cur ^ 1) * BUF_B);
            (void)nbase;
            uint32_t d0 = nb + 2 * A_TILE + wstore;
            cpasync16(d0,      whp + o);
            cpasync16(d0 + 16, whp + o + 8);
            uint32_t d1 = nb + 2 * A_TILE + W_TILE + wstore;
            cpasync16(d1,      wlp + o);
            cpasync16(d1 + 16, wlp + o + 8);
            CP_COMMIT();
            // prefetch A chunk c+1 into registers
            if (a_ok) {
                *(float4*)(af + 0) = *(const float4*)(aptr + o + 0);
                *(float4*)(af + 4) = *(const float4*)(aptr + o + 4);
            }
        }

        const uint32_t bb = sb + (uint32_t)(cur * BUF_B);
#pragma unroll
        for (int ks = 0; ks < 2; ks++) {
            const uint32_t ko = (uint32_t)(ks * 32);   // k16 slice byte offset
            uint32_t ah[4][4], al[4][4];
#pragma unroll
            for (int mt = 0; mt < 4; mt++) {
                uint32_t off = (uint32_t)((wm * 64 + mt * 16) * ROWB) + frag_off + ko;
                ldsm4(ah[mt][0], ah[mt][1], ah[mt][2], ah[mt][3], bb + 0 * A_TILE + off);
                ldsm4(al[mt][0], al[mt][1], al[mt][2], al[mt][3], bb + 1 * A_TILE + off);
            }
            uint32_t bh[2][2][2], bl[2][2][2];
#pragma unroll
            for (int np = 0; np < 2; np++) {
                uint32_t off = (uint32_t)((wn * 32 + np * 16) * ROWB) + frag_off + ko;
                uint32_t r0, r1, r2, r3;
                ldsm4(r0, r1, r2, r3, bb + 2 * A_TILE + off);
                bh[np][0][0] = r0; bh[np][0][1] = r2;
                bh[np][1][0] = r1; bh[np][1][1] = r3;
                ldsm4(r0, r1, r2, r3, bb + 2 * A_TILE + W_TILE + off);
                bl[np][0][0] = r0; bl[np][0][1] = r2;
                bl[np][1][0] = r1; bl[np][1][1] = r3;
            }
#pragma unroll
            for (int mt = 0; mt < 4; mt++) {
#pragma unroll
                for (int nt = 0; nt < 4; nt++) {
                    int np = nt >> 1, ni = nt & 1;
                    mma16816(acc[mt][nt], ah[mt], bh[np][ni][0], bh[np][ni][1]);
                    mma16816(acc[mt][nt], al[mt], bh[np][ni][0], bh[np][ni][1]);
                    mma16816(acc[mt][nt], ah[mt], bl[np][ni][0], bl[np][ni][1]);
                }
            }
        }
    }

    // epilogue: bias + store (and snapshot for rows < S)
    float* snap = (float*)g_snap;
#pragma unroll
    for (int mt = 0; mt < 4; mt++) {
        int r0 = row0 + wm * 64 + mt * 16 + (lane >> 2);
        int r1 = r0 + 8;
#pragma unroll
        for (int nt = 0; nt < 4; nt++) {
            int cb = wn * 32 + nt * 8 + 2 * (lane & 3);
            float b0 = bias[cb], b1 = bias[cb + 1];
            if (r0 < M) {
                float2 o = make_float2(acc[mt][nt][0] + b0, acc[mt][nt][1] + b1);
                *(float2*)(C + (size_t)r0 * D + cb) = o;
                if (r0 < S) *(float2*)(snap + (size_t)r0 * D + cb) = o;
            }
            if (r1 < M) {
                float2 o = make_float2(acc[mt][nt][2] + b0, acc[mt][nt][3] + b1);
                *(float2*)(C + (size_t)r1 * D + cb) = o;
                if (r1 < S) *(float2*)(snap + (size_t)r1 * D + cb) = o;
            }
        }
    }
}

// ---------------------------------------------------------------------------
// Kernel 2 (fused agg + scatter): for each source s (src_idx unique):
//   r = src_idx[s]; val = pre-update row r (snap if r < S else C)
//   o = LeakyReLU(sum_k mask[s,k] * feat(nb) + val), feat(nb) = nb<S ? snap : C
//   C[r] = val + o
// ---------------------------------------------------------------------------
__global__ __launch_bounds__(256) void agg_kernel(
    float4* __restrict__ sup,
    const int* __restrict__ src_idx,
    const int* __restrict__ neighs,
    const float* __restrict__ mask,
    int S)
{
    __shared__ int   nb[4][KNB];
    __shared__ float mk[4][KNB];
    __shared__ int   src[4];

    const int s_base = blockIdx.x * 4;
    const int tid = threadIdx.x;

    if (tid < 64) {
        int sl = tid >> 4, k = tid & 15;
        int s = s_base + sl;
        if (s < S) nb[sl][k] = neighs[(size_t)s * KNB + k];
    } else if (tid < 128) {
        int u = tid - 64;
        int sl = u >> 4, k = u & 15;
        int s = s_base + sl;
        if (s < S) mk[sl][k] = mask[(size_t)s * KNB + k];
    } else if (tid < 132) {
        int sl = tid - 128;
        int s = s_base + sl;
        if (s < S) src[sl] = src_idx[s];
    }
    __syncthreads();

    const int sl = tid >> 6;
    const int q  = tid & 63;
    const int s  = s_base + sl;
    if (s >= S) return;

    const float4* snap = (const float4*)g_snap;

    float4 v[KNB];
#pragma unroll
    for (int k = 0; k < KNB; k++) {
        int n = nb[sl][k];
        const float4* basep = (n < S) ? snap : sup;
        v[k] = basep[(size_t)n * (D / 4) + q];
    }
    const int r = src[sl];
    float4 val = (r < S) ? snap[(size_t)r * (D / 4) + q]
                         : sup[(size_t)r * (D / 4) + q];

    float4 acc = val;
#pragma unroll
    for (int k = 0; k < KNB; k++) {
        float m = mk[sl][k];
        acc.x = fmaf(m, v[k].x, acc.x);
        acc.y = fmaf(m, v[k].y, acc.y);
        acc.z = fmaf(m, v[k].z, acc.z);
        acc.w = fmaf(m, v[k].w, acc.w);
    }
    acc.x = acc.x >= 0.f ? acc.x : 0.2f * acc.x;
    acc.y = acc.y >= 0.f ? acc.y : 0.2f * acc.y;
    acc.z = acc.z >= 0.f ? acc.z : 0.2f * acc.z;
    acc.w = acc.w >= 0.f ? acc.w : 0.2f * acc.w;

    float4 o;
    o.x = val.x + acc.x; o.y = val.y + acc.y;
    o.z = val.z + acc.z; o.w = val.w + acc.w;
    sup[(size_t)r * (D / 4) + q] = o;
}

// ---------------------------------------------------------------------------
extern "C" void kernel_launch(void* const* d_in, const int* in_sizes, int n_in,
                              void* d_out, int out_size)
{
    const float* wv     = (const float*)d_in[0];
    const int*   src    = (const int*)d_in[1];
    const int*   neighs = (const int*)d_in[2];
    const float* mask   = (const float*)d_in[3];
    const float* W      = (const float*)d_in[4];
    const float* bias   = (const float*)d_in[5];
    float*       out    = (float*)d_out;

    const int N = in_sizes[0] / D;
    const int S = in_sizes[1];

    // 0) split W to bf16 hi/lo (tiny)
    {
        __nv_bfloat16 *whi, *wlo;
        cudaGetSymbolAddress((void**)&whi, g_Whi);
        cudaGetSymbolAddress((void**)&wlo, g_Wlo);
        int w8 = D * (D / 8);
        splitW_kernel<<<(w8 + 255) / 256, 256>>>(W, (uint4*)whi, (uint4*)wlo, w8);
    }

    // 1) tensor-core GEMM + bias -> out (+ snapshot rows < S)
    cudaFuncSetAttribute(gemm_mma_kernel, cudaFuncAttributeMaxDynamicSharedMemorySize,
                         SMEM_GEMM_TOTAL);
    gemm_mma_kernel<<<(N + 127) / 128, 512, SMEM_GEMM_TOTAL>>>(wv, bias, out, N, S);

    // 2) fused aggregation + residual + LeakyReLU + in-place scatter-add
    agg_kernel<<<(S + 3) / 4, 256>>>((float4*)out, src, neighs, mask, S);
}